// round 1
// baseline (speedup 1.0000x reference)
#include <cuda_runtime.h>
#include <math.h>

#define NB 2
#define NN 20001
#define NE 500000
#define MAXNODES 1024
#define MAXE1 65536
#define MAXL2 8192
#define SCALEF 22.62741699796952f
#define LN_EPS 1e-6f
#define ALPHA 0.2f

// ---------------- scratch (device globals; no allocs) ----------------
__device__ int   g_map[NB * NN];            // 0 = absent, else local_idx+1
__device__ int   g_nodes[NB * MAXNODES];
__device__ int   g_nn[NB];
__device__ int   g_c1[NB];
__device__ int   g_c2[NB];
__device__ int   g_l2dst[NB * MAXL2];
__device__ int   g_e1src[NB * MAXE1];       // local src index
__device__ int   g_e1dst[NB * MAXE1];       // global dst node
__device__ float g_u1[4 * 256], g_v1[4 * 256], g_c1s[4], g_d1s[4];
__device__ float g_u2[4 * 512], g_v2[4 * 512], g_c2s[4], g_d2s[4];
__device__ float g_sA1[NB * MAXNODES * 4];
__device__ float g_rs1[NB * MAXNODES * 4];
__device__ float g_agg1[NB * MAXNODES * 1024];  // [node][h][256]
__device__ float g_hcat[NB * MAXNODES * 512];
__device__ float g_sA2[NB * 4];
__device__ float g_rs2[NB * 4];
__device__ float g_agg2[NB * 4 * 512];

// ---------------- helpers ----------------
__device__ __forceinline__ float warp_sum(float v) {
#pragma unroll
    for (int o = 16; o > 0; o >>= 1) v += __shfl_xor_sync(0xffffffffu, v, o);
    return v;
}

// blockDim.x threads, sm must have >= 33 floats
__device__ float block_sum(float v, float* sm) {
    int tid = threadIdx.x, w = tid >> 5, l = tid & 31, nw = blockDim.x >> 5;
    v = warp_sum(v);
    if (l == 0) sm[w] = v;
    __syncthreads();
    if (w == 0) {
        float r = (l < nw) ? sm[l] : 0.f;
        r = warp_sum(r);
        if (l == 0) sm[32] = r;
    }
    __syncthreads();
    float out = sm[32];
    __syncthreads();
    return out;
}

__device__ __forceinline__ float lrelu_scale_exp(float s) {
    float t = (s > 0.f) ? s : (ALPHA * s);
    return expf(t / SCALEF);
}

// ---------------- K0: zero per-replay state ----------------
__global__ void k0_init() {
    int gid = blockIdx.x * blockDim.x + threadIdx.x;
    int stride = gridDim.x * blockDim.x;
    for (int i = gid; i < NB * NN; i += stride) g_map[i] = 0;
    for (int i = gid; i < NB * 4 * 512; i += stride) g_agg2[i] = 0.f;
    if (gid < NB) { g_nn[gid] = 0; g_c1[gid] = 0; g_c2[gid] = 0; }
    if (gid < NB * 4) g_rs2[gid] = 0.f;
}

// ---------------- Kprep: u/v = a^T W folded vectors ----------------
__global__ void k_prep(const float* __restrict__ W1, const float* __restrict__ b1,
                       const float* __restrict__ a1,
                       const float* __restrict__ W2, const float* __restrict__ b2,
                       const float* __restrict__ a2) {
    int gid = blockIdx.x * blockDim.x + threadIdx.x;
    if (gid < 1024) {
        int h = gid >> 8, k = gid & 255;
        float au = 0.f, av = 0.f;
#pragma unroll 4
        for (int j = 0; j < 128; j++) {
            float w = W1[(h * 128 + j) * 256 + k];
            au += a1[h * 256 + j] * w;
            av += a1[h * 256 + 128 + j] * w;
        }
        g_u1[h * 256 + k] = au;
        g_v1[h * 256 + k] = av;
    } else if (gid < 3072) {
        int g2i = gid - 1024;
        int h = g2i >> 9, k = g2i & 511;
        float au = 0.f, av = 0.f;
#pragma unroll 4
        for (int j = 0; j < 128; j++) {
            float w = W2[(h * 128 + j) * 512 + k];
            au += a2[h * 256 + j] * w;
            av += a2[h * 256 + 128 + j] * w;
        }
        g_u2[h * 512 + k] = au;
        g_v2[h * 512 + k] = av;
    }
    if (gid < 4) {
        int h = gid;
        float c1v = 0.f, d1v = 0.f, c2v = 0.f, d2v = 0.f;
        for (int j = 0; j < 128; j++) {
            c1v += a1[h * 256 + j] * b1[h * 128 + j];
            d1v += a1[h * 256 + 128 + j] * b1[h * 128 + j];
            c2v += a2[h * 256 + j] * b2[h * 128 + j];
            d2v += a2[h * 256 + 128 + j] * b2[h * 128 + j];
        }
        g_c1s[h] = c1v; g_d1s[h] = d1v; g_c2s[h] = c2v; g_d2s[h] = d2v;
    }
}

// ---------------- K1: scan edge_out for src == N-1 ----------------
__global__ void k1_scan_out(const int* __restrict__ eo) {
    int gid = blockIdx.x * blockDim.x + threadIdx.x;
    int stride = gridDim.x * blockDim.x;
    for (int i = gid; i < NB * NE; i += stride) {
        int b = (i >= NE) ? 1 : 0;
        int e = i - b * NE;
        int src = eo[(b * 2) * NE + e];
        if (src == NN - 1) {
            int p = atomicAdd(&g_c2[b], 1);
            if (p < MAXL2) g_l2dst[b * MAXL2 + p] = eo[(b * 2 + 1) * NE + e];
        }
    }
}

// ---------------- K2a: build unique node set (dsts + node N-1) -------
__global__ void k2a_nodes() {
    int b = blockIdx.x;
    int cnt = min(g_c2[b], MAXL2);
    for (int i = threadIdx.x; i <= cnt; i += blockDim.x) {
        int node = (i == cnt) ? (NN - 1) : g_l2dst[b * MAXL2 + i];
        if (atomicCAS(&g_map[b * NN + node], 0, 1) == 0) {
            int p = atomicAdd(&g_nn[b], 1);
            if (p < MAXNODES) g_nodes[b * MAXNODES + p] = node;
        }
    }
}

// ---------------- K2b: index the map + zero per-node accumulators ----
__global__ void k2b_index() {
    int b = blockIdx.x;
    int nnr = min(g_nn[b], MAXNODES);
    for (int ln = threadIdx.x; ln < nnr; ln += blockDim.x)
        g_map[b * NN + g_nodes[b * MAXNODES + ln]] = ln + 1;
    for (int k = threadIdx.x; k < nnr * 1024; k += blockDim.x)
        g_agg1[b * MAXNODES * 1024 + k] = 0.f;
    for (int k = threadIdx.x; k < nnr * 4; k += blockDim.x)
        g_rs1[b * MAXNODES * 4 + k] = 0.f;
}

// ---------------- K3: scan edge_in for src in node set ---------------
__global__ void k3_scan_in(const int* __restrict__ ei) {
    int gid = blockIdx.x * blockDim.x + threadIdx.x;
    int stride = gridDim.x * blockDim.x;
    for (int i = gid; i < NB * NE; i += stride) {
        int b = (i >= NE) ? 1 : 0;
        int e = i - b * NE;
        int src = ei[(b * 2) * NE + e];
        int m = g_map[b * NN + src];
        if (m > 0) {
            int p = atomicAdd(&g_c1[b], 1);
            if (p < MAXE1) {
                g_e1src[b * MAXE1 + p] = m - 1;
                g_e1dst[b * MAXE1 + p] = ei[(b * 2 + 1) * NE + e];
            }
        }
    }
}

// ---------------- K4: sA1 per set node: emb[node]·u1[h] + c1s --------
__global__ void k4_sA1(const float* __restrict__ embed) {
    int b = blockIdx.x & 1;
    int slot = blockIdx.x >> 1;
    int nslots = gridDim.x >> 1;
    int h = threadIdx.x >> 5, lane = threadIdx.x & 31;
    int nnr = min(g_nn[b], MAXNODES);
    for (int ln = slot; ln < nnr; ln += nslots) {
        int node = g_nodes[b * MAXNODES + ln];
        const float* er = embed + (size_t)node * 256;
        float acc = 0.f;
#pragma unroll
        for (int t = 0; t < 8; t++) {
            int k = lane + 32 * t;
            acc += er[k] * g_u1[h * 256 + k];
        }
        acc = warp_sum(acc);
        if (lane == 0) g_sA1[(b * MAXNODES + ln) * 4 + h] = acc + g_c1s[h];
    }
}

// ---------------- K5: layer-1 edge aggregation (warp per edge) -------
__global__ void k5_edges1(const float* __restrict__ embed) {
    int gw = blockIdx.x * (blockDim.x >> 5) + (threadIdx.x >> 5);
    int nw = gridDim.x * (blockDim.x >> 5);
    int lane = threadIdx.x & 31;
    for (int b = 0; b < NB; b++) {
        int cnt = min(g_c1[b], MAXE1);
        for (int i = gw; i < cnt; i += nw) {
            int lsrc = g_e1src[b * MAXE1 + i];
            int dst = g_e1dst[b * MAXE1 + i];
            const float* er = embed + (size_t)dst * 256;
            float emb[8];
#pragma unroll
            for (int t = 0; t < 8; t++) emb[t] = er[lane + 32 * t];
#pragma unroll
            for (int h = 0; h < 4; h++) {
                float a = 0.f;
#pragma unroll
                for (int t = 0; t < 8; t++) a += emb[t] * g_v1[h * 256 + lane + 32 * t];
                a = warp_sum(a);
                float s = g_sA1[(b * MAXNODES + lsrc) * 4 + h] + a + g_d1s[h];
                float ev = lrelu_scale_exp(s);
                if (lane == 0) atomicAdd(&g_rs1[(b * MAXNODES + lsrc) * 4 + h], ev);
                float* ag = &g_agg1[(b * MAXNODES + lsrc) * 1024 + h * 256];
#pragma unroll
                for (int t = 0; t < 8; t++) atomicAdd(&ag[lane + 32 * t], ev * emb[t]);
            }
        }
    }
}

// ---------------- K6: per-node projection + LN + elu -> hcat ---------
__global__ void __launch_bounds__(512) k6_proj1(const float* __restrict__ W1,
                                                const float* __restrict__ b1,
                                                const float* __restrict__ g1,
                                                const float* __restrict__ bn1) {
    __shared__ float sag[1024];
    __shared__ float sred[33];
    int t = threadIdx.x;
    int h = t >> 7, j = t & 127;
    for (int b = 0; b < NB; b++) {
        int nnr = min(g_nn[b], MAXNODES);
        for (int ln = blockIdx.x; ln < nnr; ln += gridDim.x) {
            for (int k = t; k < 1024; k += blockDim.x)
                sag[k] = g_agg1[(b * MAXNODES + ln) * 1024 + k];
            __syncthreads();
            float rs = g_rs1[(b * MAXNODES + ln) * 4 + h];
            float rsp = (rs == 0.f) ? 1.f : rs;
            const float* wr = W1 + (h * 128 + j) * 256;
            const float* ag = &sag[h * 256];
            float acc = 0.f;
#pragma unroll 8
            for (int k = 0; k < 256; k++) acc += wr[k] * ag[k];
            float val = (acc + rs * b1[h * 128 + j]) / rsp;
            // layernorm over 512 (torch ddof=1, eps on std)
            float tot = block_sum(val, sred);
            float m = tot * (1.f / 512.f);
            float dv = val - m;
            float sq = block_sum(dv * dv, sred);
            float stdv = sqrtf(sq * (1.f / 511.f));
            float y = g1[t] * dv / (stdv + LN_EPS) + bn1[t];
            float e = (y > 0.f) ? y : expm1f(y);
            g_hcat[(b * MAXNODES + ln) * 512 + t] = e;
            __syncthreads();
        }
    }
}

// ---------------- K7a: sA2 at node N-1 -------------------------------
__global__ void k7a_sA2() {
    int b = blockIdx.x;
    int h = threadIdx.x >> 5, lane = threadIdx.x & 31;
    int ln = g_map[b * NN + (NN - 1)] - 1;
    if (ln < 0) ln = 0;  // cannot happen
    const float* hc = &g_hcat[(b * MAXNODES + ln) * 512];
    float acc = 0.f;
#pragma unroll
    for (int t = 0; t < 16; t++) {
        int k = lane + 32 * t;
        acc += hc[k] * g_u2[h * 512 + k];
    }
    acc = warp_sum(acc);
    if (lane == 0) g_sA2[b * 4 + h] = acc + g_c2s[h];
}

// ---------------- K7: layer-2 edge aggregation (warp per edge) -------
__global__ void k7_edges2() {
    int gw = blockIdx.x * (blockDim.x >> 5) + (threadIdx.x >> 5);
    int nw = gridDim.x * (blockDim.x >> 5);
    int lane = threadIdx.x & 31;
    for (int b = 0; b < NB; b++) {
        int cnt = min(g_c2[b], MAXL2);
        for (int i = gw; i < cnt; i += nw) {
            int dst = g_l2dst[b * MAXL2 + i];
            int ln = g_map[b * NN + dst] - 1;
            const float* hc = &g_hcat[(b * MAXNODES + ln) * 512];
            float hv[16];
#pragma unroll
            for (int t = 0; t < 16; t++) hv[t] = hc[lane + 32 * t];
#pragma unroll
            for (int h = 0; h < 4; h++) {
                float a = 0.f;
#pragma unroll
                for (int t = 0; t < 16; t++) a += hv[t] * g_v2[h * 512 + lane + 32 * t];
                a = warp_sum(a);
                float s = g_sA2[b * 4 + h] + a + g_d2s[h];
                float ev = lrelu_scale_exp(s);
                if (lane == 0) atomicAdd(&g_rs2[b * 4 + h], ev);
                float* ag = &g_agg2[(b * 4 + h) * 512];
#pragma unroll
                for (int t = 0; t < 16; t++) atomicAdd(&ag[lane + 32 * t], ev * hv[t]);
            }
        }
    }
}

// ---------------- K8: final projection + LN + relu + head -> out -----
__global__ void __launch_bounds__(512) k8_final(const float* __restrict__ W2,
                                                const float* __restrict__ b2,
                                                const float* __restrict__ g2,
                                                const float* __restrict__ bn2,
                                                const float* __restrict__ Vw,
                                                const float* __restrict__ Vb,
                                                float* __restrict__ out) {
    __shared__ float sag[2048];
    __shared__ float sp[512];
    __shared__ float sred[33];
    int b = blockIdx.x;
    int t = threadIdx.x;
    int h = t >> 7, j = t & 127;
    for (int k = t; k < 2048; k += blockDim.x) sag[k] = g_agg2[b * 2048 + k];
    __syncthreads();
    float rs = g_rs2[b * 4 + h];
    float rsp = (rs == 0.f) ? 1.f : rs;
    const float* wr = W2 + (h * 128 + j) * 512;
    const float* ag = &sag[h * 512];
    float acc = 0.f;
#pragma unroll 8
    for (int k = 0; k < 512; k++) acc += wr[k] * ag[k];
    sp[t] = (acc + rs * b2[h * 128 + j]) / rsp;
    __syncthreads();
    float v = 0.f;
    if (t < 128) v = 0.25f * (sp[t] + sp[128 + t] + sp[256 + t] + sp[384 + t]);
    float tot = block_sum((t < 128) ? v : 0.f, sred);
    float m = tot * (1.f / 128.f);
    float dv = (t < 128) ? (v - m) : 0.f;
    float sq = block_sum(dv * dv, sred);
    float stdv = sqrtf(sq * (1.f / 127.f));
    float r0 = 0.f, r1 = 0.f;
    if (t < 128) {
        float y = g2[t] * dv / (stdv + LN_EPS) + bn2[t];
        float r = (y > 0.f) ? y : 0.f;
        r0 = r * Vw[t];
        r1 = r * Vw[128 + t];
    }
    float o0 = block_sum(r0, sred);
    float o1 = block_sum(r1, sred);
    if (t == 0) {
        out[b * 2 + 0] = o0 + Vb[0];
        out[b * 2 + 1] = o1 + Vb[1];
    }
}

// ---------------- launch ----------------
extern "C" void kernel_launch(void* const* d_in, const int* in_sizes, int n_in,
                              void* d_out, int out_size) {
    const int* edge_in = (const int*)d_in[0];
    const int* edge_out = (const int*)d_in[1];
    const float* embed = (const float*)d_in[2];
    const float* W1 = (const float*)d_in[3];
    const float* b1 = (const float*)d_in[4];
    const float* a1 = (const float*)d_in[5];
    const float* g1 = (const float*)d_in[6];
    const float* bn1 = (const float*)d_in[7];
    const float* W2 = (const float*)d_in[8];
    const float* b2 = (const float*)d_in[9];
    const float* a2 = (const float*)d_in[10];
    const float* g2 = (const float*)d_in[11];
    const float* bn2 = (const float*)d_in[12];
    const float* Vw = (const float*)d_in[13];
    const float* Vb = (const float*)d_in[14];
    float* out = (float*)d_out;

    k0_init<<<64, 256>>>();
    k_prep<<<12, 256>>>(W1, b1, a1, W2, b2, a2);
    k1_scan_out<<<512, 256>>>(edge_out);
    k2a_nodes<<<NB, 256>>>();
    k2b_index<<<NB, 1024>>>();
    k3_scan_in<<<512, 256>>>(edge_in);
    k4_sA1<<<32, 128>>>(embed);
    k5_edges1<<<128, 256>>>(embed);
    k6_proj1<<<64, 512>>>(W1, b1, g1, bn1);
    k7a_sA2<<<NB, 128>>>();
    k7_edges2<<<32, 256>>>();
    k8_final<<<NB, 512>>>(W2, b2, g2, bn2, Vw, Vb, out);
}

// round 2
// speedup vs baseline: 3.2331x; 3.2331x over previous
#include <cuda_runtime.h>
#include <math.h>

#define NB 2
#define NN 20001
#define NE 500000
#define MAXL2 4096
#define MAXNODES (MAXL2 + 1)   // every dedup winner fits -> cleanup is exact
#define MAXE1 65536
#define MAXEPN 1024            // per-node layer-1 edge cap (expected ~25)
#define CH2 256                // layer-2 edge chunk
#define SCALEF 22.62741699796952f
#define LN_EPS 1e-6f
#define ALPHA 0.2f

// ---------------- scratch (device globals; zero-init on load) ----------------
__device__ int   g_map[NB * NN];          // 0 = absent, else local_idx+1
__device__ int   g_nodes[NB * MAXNODES];
__device__ int   g_nn[NB];
__device__ int   g_c1[NB];
__device__ int   g_c2[NB];
__device__ int   g_l2dst[NB * MAXL2];
__device__ int   g_e1src[NB * MAXE1];
__device__ int   g_e1dst[NB * MAXE1];
__device__ float g_u1[4 * 256], g_v1[4 * 256], g_c1s[4], g_d1s[4];
__device__ float g_u2[4 * 512], g_v2[4 * 512], g_c2s[4], g_d2s[4];
__device__ float g_hcat[(size_t)NB * MAXNODES * 512];

// ---------------- helpers ----------------
__device__ __forceinline__ float warp_sum(float v) {
#pragma unroll
    for (int o = 16; o > 0; o >>= 1) v += __shfl_xor_sync(0xffffffffu, v, o);
    return v;
}

__device__ float block_sum(float v, float* sm) {
    int tid = threadIdx.x, w = tid >> 5, l = tid & 31, nw = blockDim.x >> 5;
    v = warp_sum(v);
    if (l == 0) sm[w] = v;
    __syncthreads();
    if (w == 0) {
        float r = (l < nw) ? sm[l] : 0.f;
        r = warp_sum(r);
        if (l == 0) sm[32] = r;
    }
    __syncthreads();
    float out = sm[32];
    __syncthreads();
    return out;
}

__device__ __forceinline__ float lrelu_scale_exp(float s) {
    float t = (s > 0.f) ? s : (ALPHA * s);
    return expf(t / SCALEF);
}

// ============ K_A: fold a^T.W prep  +  scan edge_out for src==N-1 ============
__global__ void kA(const int* __restrict__ eo,
                   const float* __restrict__ W1, const float* __restrict__ b1,
                   const float* __restrict__ a1,
                   const float* __restrict__ W2, const float* __restrict__ b2,
                   const float* __restrict__ a2) {
    int gid = blockIdx.x * blockDim.x + threadIdx.x;
    int stride = gridDim.x * blockDim.x;

    if (gid < 1024) {                       // u1/v1 = a1^T W1  (coalesced over k)
        int h = gid >> 8, k = gid & 255;
        float au = 0.f, av = 0.f;
#pragma unroll 4
        for (int j = 0; j < 128; j++) {
            float w = W1[(h * 128 + j) * 256 + k];
            au += a1[h * 256 + j] * w;
            av += a1[h * 256 + 128 + j] * w;
        }
        g_u1[h * 256 + k] = au;
        g_v1[h * 256 + k] = av;
    } else if (gid < 3072) {                // u2/v2 = a2^T W2
        int g2i = gid - 1024;
        int h = g2i >> 9, k = g2i & 511;
        float au = 0.f, av = 0.f;
#pragma unroll 4
        for (int j = 0; j < 128; j++) {
            float w = W2[(h * 128 + j) * 512 + k];
            au += a2[h * 256 + j] * w;
            av += a2[h * 256 + 128 + j] * w;
        }
        g_u2[h * 512 + k] = au;
        g_v2[h * 512 + k] = av;
    }
    if (gid < 4) {
        int h = gid;
        float c1v = 0.f, d1v = 0.f, c2v = 0.f, d2v = 0.f;
        for (int j = 0; j < 128; j++) {
            c1v += a1[h * 256 + j] * b1[h * 128 + j];
            d1v += a1[h * 256 + 128 + j] * b1[h * 128 + j];
            c2v += a2[h * 256 + j] * b2[h * 128 + j];
            d2v += a2[h * 256 + 128 + j] * b2[h * 128 + j];
        }
        g_c1s[h] = c1v; g_d1s[h] = d1v; g_c2s[h] = c2v; g_d2s[h] = d2v;
    }

    // scan edge_out (counters were reset by previous replay's kE / static init)
    for (int i = gid; i < NB * NE; i += stride) {
        int b = (i >= NE) ? 1 : 0;
        int e = i - b * NE;
        int src = eo[(size_t)(2 * b) * NE + e];
        if (src == NN - 1) {
            int p = atomicAdd(&g_c2[b], 1);
            if (p < MAXL2) g_l2dst[b * MAXL2 + p] = eo[(size_t)(2 * b + 1) * NE + e];
        }
    }
}

// ============ K_B: dedupe dsts + node N-1, index the map ============
__global__ void kB() {
    int b = blockIdx.x, t = threadIdx.x;
    int cnt = min(g_c2[b], MAXL2);
    for (int i = t; i <= cnt; i += blockDim.x) {
        int node = (i == cnt) ? (NN - 1) : g_l2dst[b * MAXL2 + i];
        if (atomicCAS(&g_map[b * NN + node], 0, 1) == 0) {
            int p = atomicAdd(&g_nn[b], 1);
            g_nodes[b * MAXNODES + p] = node;    // p <= MAXL2 < MAXNODES guaranteed
        }
    }
    __syncthreads();
    int nnr = g_nn[b];
    for (int i = t; i < nnr; i += blockDim.x)
        g_map[b * NN + g_nodes[b * MAXNODES + i]] = i + 1;
}

// ============ K_C: scan edge_in for src in node set ============
__global__ void kC(const int* __restrict__ ei) {
    int gid = blockIdx.x * blockDim.x + threadIdx.x;
    int stride = gridDim.x * blockDim.x;
    for (int i = gid; i < NB * NE; i += stride) {
        int b = (i >= NE) ? 1 : 0;
        int e = i - b * NE;
        int src = ei[(size_t)(2 * b) * NE + e];
        int m = g_map[b * NN + src];
        if (m > 0) {
            int p = atomicAdd(&g_c1[b], 1);
            if (p < MAXE1) {
                g_e1src[b * MAXE1 + p] = m - 1;
                g_e1dst[b * MAXE1 + p] = ei[(size_t)(2 * b + 1) * NE + e];
            }
        }
    }
}

// ============ K_D: layer-1, one block per node (smem-only accumulation) ======
__global__ void __launch_bounds__(512) kD(const float* __restrict__ embed,
                                          const float* __restrict__ W1,
                                          const float* __restrict__ b1,
                                          const float* __restrict__ g1,
                                          const float* __restrict__ bn1) {
    __shared__ float s_ev[MAXEPN * 4];
    __shared__ int   s_dst[MAXEPN];
    __shared__ float s_agg[1024];
    __shared__ float s_out[512];
    __shared__ float s_x[256];
    __shared__ float s_sA[4];
    __shared__ float s_rs[4];
    __shared__ float s_red[33];
    __shared__ int   s_m;

    int b = blockIdx.x & 1, slot = blockIdx.x >> 1, nslots = gridDim.x >> 1;
    int t = threadIdx.x, lane = t & 31, w = t >> 5;
    int nnr = min(g_nn[b], MAXNODES);
    int cnt = min(g_c1[b], MAXE1);

    for (int ln = slot; ln < nnr; ln += nslots) {
        if (t == 0) s_m = 0;
        __syncthreads();
        // collect this node's edges
        for (int i = t; i < cnt; i += 512)
            if (g_e1src[b * MAXE1 + i] == ln) {
                int p = atomicAdd(&s_m, 1);
                if (p < MAXEPN) s_dst[p] = g_e1dst[b * MAXE1 + i];
            }
        int node = g_nodes[b * MAXNODES + ln];
        if (t < 256) s_x[t] = embed[(size_t)node * 256 + t];
        __syncthreads();
        int m = min(s_m, MAXEPN);

        // sA1[h] = emb[node].u1[h] + c1s[h]   (warp per head)
        if (w < 4) {
            float a = 0.f;
#pragma unroll
            for (int q = 0; q < 8; q++) a += s_x[lane + 32 * q] * g_u1[w * 256 + lane + 32 * q];
            a = warp_sum(a);
            if (lane == 0) s_sA[w] = a + g_c1s[w];
        }
        __syncthreads();

        // per-edge attention weight (warp per edge)
        for (int e = w; e < m; e += 16) {
            const float* er = embed + (size_t)s_dst[e] * 256;
            float ev8[8];
#pragma unroll
            for (int q = 0; q < 8; q++) ev8[q] = er[lane + 32 * q];
#pragma unroll
            for (int h = 0; h < 4; h++) {
                float a = 0.f;
#pragma unroll
                for (int q = 0; q < 8; q++) a += ev8[q] * g_v1[h * 256 + lane + 32 * q];
                a = warp_sum(a);
                if (lane == 0) s_ev[e * 4 + h] = lrelu_scale_exp(s_sA[h] + a + g_d1s[h]);
            }
        }
        __syncthreads();

        // rowsums (warp per head)
        if (w < 4) {
            float r = 0.f;
            for (int e = lane; e < m; e += 32) r += s_ev[e * 4 + w];
            r = warp_sum(r);
            if (lane == 0) s_rs[w] = r;
        }
        __syncthreads();

        // aggregate in embedding space: thread t owns (h=t>>8,c=t&255) and (h+2,c)
        int c = t & 255, h0 = t >> 8;
        float a0 = 0.f, a1v = 0.f;
        for (int e = 0; e < m; e++) {
            float x = embed[(size_t)s_dst[e] * 256 + c];
            a0  += s_ev[e * 4 + h0]     * x;
            a1v += s_ev[e * 4 + h0 + 2] * x;
        }
        s_agg[h0 * 256 + c] = a0;
        s_agg[(h0 + 2) * 256 + c] = a1v;
        __syncthreads();

        // projection: warp per output row (coalesced float4 W1 loads)
        for (int r = w; r < 512; r += 16) {
            int h = r >> 7;
            const float4* wr = (const float4*)(W1 + (size_t)r * 256);
            const float4* ag = (const float4*)(s_agg + h * 256);
            float acc = 0.f;
#pragma unroll
            for (int q = 0; q < 2; q++) {
                float4 wv = wr[lane + 32 * q];
                float4 av = ag[lane + 32 * q];
                acc += wv.x * av.x + wv.y * av.y + wv.z * av.z + wv.w * av.w;
            }
            acc = warp_sum(acc);
            if (lane == 0) {
                float rs = s_rs[h];
                float rsp = (rs == 0.f) ? 1.f : rs;
                s_out[r] = (acc + rs * b1[r]) / rsp;
            }
        }
        __syncthreads();

        // layernorm(512, ddof=1, eps on std) + elu
        float val = s_out[t];
        float tot = block_sum(val, s_red);
        float mn = tot * (1.f / 512.f);
        float dv = val - mn;
        float sq = block_sum(dv * dv, s_red);
        float stdv = sqrtf(sq * (1.f / 511.f));
        float y = g1[t] * dv / (stdv + LN_EPS) + bn1[t];
        g_hcat[((size_t)b * MAXNODES + ln) * 512 + t] = (y > 0.f) ? y : expm1f(y);
        __syncthreads();
    }
}

// ============ K_E: layer-2 + final head, one block per batch + cleanup =======
__global__ void __launch_bounds__(512) kE(const float* __restrict__ W2,
                                          const float* __restrict__ b2,
                                          const float* __restrict__ g2,
                                          const float* __restrict__ bn2,
                                          const float* __restrict__ Vw,
                                          const float* __restrict__ Vb,
                                          float* __restrict__ out) {
    __shared__ float s_ev[CH2 * 4];
    __shared__ int   s_ln[CH2];
    __shared__ float s_agg[2048];
    __shared__ float s_p[512];
    __shared__ float s_x[512];
    __shared__ float s_sA[4];
    __shared__ float s_rs[4];
    __shared__ float s_red[33];

    int b = blockIdx.x;
    int t = threadIdx.x, lane = t & 31, w = t >> 5;
    int cnt = min(g_c2[b], MAXL2);
    int ln0 = g_map[b * NN + (NN - 1)] - 1;
    if (ln0 < 0) ln0 = 0;

    s_x[t] = g_hcat[((size_t)b * MAXNODES + ln0) * 512 + t];
    if (t < 4) s_rs[t] = 0.f;
    __syncthreads();
    if (w < 4) {
        float a = 0.f;
#pragma unroll
        for (int q = 0; q < 16; q++) a += s_x[lane + 32 * q] * g_u2[w * 512 + lane + 32 * q];
        a = warp_sum(a);
        if (lane == 0) s_sA[w] = a + g_c2s[w];
    }
    __syncthreads();

    float acc[4] = {0.f, 0.f, 0.f, 0.f};   // thread t owns feature c=t for all 4 heads
    for (int base = 0; base < cnt; base += CH2) {
        int mc = min(cnt - base, CH2);
        for (int e = t; e < mc; e += 512)
            s_ln[e] = g_map[b * NN + g_l2dst[b * MAXL2 + base + e]] - 1;
        __syncthreads();
        for (int e = w; e < mc; e += 16) {
            const float* hr = g_hcat + ((size_t)b * MAXNODES + s_ln[e]) * 512;
            float hv[16];
#pragma unroll
            for (int q = 0; q < 16; q++) hv[q] = hr[lane + 32 * q];
#pragma unroll
            for (int h = 0; h < 4; h++) {
                float a = 0.f;
#pragma unroll
                for (int q = 0; q < 16; q++) a += hv[q] * g_v2[h * 512 + lane + 32 * q];
                a = warp_sum(a);
                if (lane == 0) s_ev[e * 4 + h] = lrelu_scale_exp(s_sA[h] + a + g_d2s[h]);
            }
        }
        __syncthreads();
        if (w < 4) {
            float r = 0.f;
            for (int e = lane; e < mc; e += 32) r += s_ev[e * 4 + w];
            r = warp_sum(r);
            if (lane == 0) s_rs[w] += r;
        }
        for (int e = 0; e < mc; e++) {
            float x = g_hcat[((size_t)b * MAXNODES + s_ln[e]) * 512 + t];
#pragma unroll
            for (int h = 0; h < 4; h++) acc[h] += s_ev[e * 4 + h] * x;
        }
        __syncthreads();
    }
#pragma unroll
    for (int h = 0; h < 4; h++) s_agg[h * 512 + t] = acc[h];
    __syncthreads();

    // projection: warp per row (coalesced float4 W2 loads)
    for (int r = w; r < 512; r += 16) {
        int h = r >> 7;
        const float4* wr = (const float4*)(W2 + (size_t)r * 512);
        const float4* ag = (const float4*)(s_agg + h * 512);
        float a = 0.f;
#pragma unroll
        for (int q = 0; q < 4; q++) {
            float4 wv = wr[lane + 32 * q];
            float4 av = ag[lane + 32 * q];
            a += wv.x * av.x + wv.y * av.y + wv.z * av.z + wv.w * av.w;
        }
        a = warp_sum(a);
        if (lane == 0) {
            float rs = s_rs[h];
            float rsp = (rs == 0.f) ? 1.f : rs;
            s_p[r] = (a + rs * b2[r]) / rsp;
        }
    }
    __syncthreads();

    // mean over heads, layernorm(128, ddof=1), relu, final 128->2
    float v = 0.f;
    if (t < 128) v = 0.25f * (s_p[t] + s_p[128 + t] + s_p[256 + t] + s_p[384 + t]);
    float tot = block_sum((t < 128) ? v : 0.f, s_red);
    float mn = tot * (1.f / 128.f);
    float dv = (t < 128) ? (v - mn) : 0.f;
    float sq = block_sum(dv * dv, s_red);
    float stdv = sqrtf(sq * (1.f / 127.f));
    float r0 = 0.f, r1 = 0.f;
    if (t < 128) {
        float y = g2[t] * dv / (stdv + LN_EPS) + bn2[t];
        float rr = (y > 0.f) ? y : 0.f;
        r0 = rr * Vw[t];
        r1 = rr * Vw[128 + t];
    }
    float o0 = block_sum(r0, s_red);
    float o1 = block_sum(r1, s_red);
    if (t == 0) {
        out[b * 2 + 0] = o0 + Vb[0];
        out[b * 2 + 1] = o1 + Vb[1];
    }

    // self-cleaning for next replay
    __syncthreads();
    int nnr = min(g_nn[b], MAXNODES);
    for (int i = t; i < nnr; i += 512) g_map[b * NN + g_nodes[b * MAXNODES + i]] = 0;
    if (t == 0) { g_nn[b] = 0; g_c1[b] = 0; g_c2[b] = 0; }
}

// ---------------- launch ----------------
extern "C" void kernel_launch(void* const* d_in, const int* in_sizes, int n_in,
                              void* d_out, int out_size) {
    const int* edge_in = (const int*)d_in[0];
    const int* edge_out = (const int*)d_in[1];
    const float* embed = (const float*)d_in[2];
    const float* W1 = (const float*)d_in[3];
    const float* b1 = (const float*)d_in[4];
    const float* a1 = (const float*)d_in[5];
    const float* g1 = (const float*)d_in[6];
    const float* bn1 = (const float*)d_in[7];
    const float* W2 = (const float*)d_in[8];
    const float* b2 = (const float*)d_in[9];
    const float* a2 = (const float*)d_in[10];
    const float* g2 = (const float*)d_in[11];
    const float* bn2 = (const float*)d_in[12];
    const float* Vw = (const float*)d_in[13];
    const float* Vb = (const float*)d_in[14];
    float* out = (float*)d_out;

    kA<<<512, 256>>>(edge_out, W1, b1, a1, W2, b2, a2);
    kB<<<NB, 256>>>();
    kC<<<512, 256>>>(edge_in);
    kD<<<64, 512>>>(embed, W1, b1, g1, bn1);
    kE<<<NB, 512>>>(W2, b2, g2, bn2, Vw, Vb, out);
}

// round 3
// speedup vs baseline: 4.2142x; 1.3035x over previous
#include <cuda_runtime.h>
#include <math.h>

#define NB 2
#define NN 20001
#define NE 500000
#define MAXL2 4096
#define MAXNODES (MAXL2 + 1)
#define MAXE1 65536
#define MAXEPN 1024
#define SCALEF 22.62741699796952f
#define LN_EPS 1e-6f
#define ALPHA 0.2f

// ---------------- scratch (device globals; zero-init on load) ----------------
__device__ int   g_map[NB * NN];          // 0 = absent, else local_idx+1
__device__ int   g_nodes[NB * MAXNODES];
__device__ int   g_nn[NB];
__device__ int   g_c1[NB];
__device__ int   g_c2[NB];
__device__ int   g_l2dst[NB * MAXL2];
__device__ int   g_e1src[NB * MAXE1];
__device__ int   g_e1dst[NB * MAXE1];
__device__ float g_u1[4 * 256], g_v1[4 * 256], g_c1s[4], g_d1s[4];
__device__ float g_u2[4 * 512], g_v2[4 * 512], g_c2s[4], g_d2s[4];
__device__ float g_hcat[(size_t)NB * MAXNODES * 512];

// ---------------- helpers ----------------
__device__ __forceinline__ float warp_sum(float v) {
#pragma unroll
    for (int o = 16; o > 0; o >>= 1) v += __shfl_xor_sync(0xffffffffu, v, o);
    return v;
}

__device__ float block_sum(float v, float* sm) {
    int tid = threadIdx.x, w = tid >> 5, l = tid & 31, nw = blockDim.x >> 5;
    v = warp_sum(v);
    if (l == 0) sm[w] = v;
    __syncthreads();
    if (w == 0) {
        float r = (l < nw) ? sm[l] : 0.f;
        r = warp_sum(r);
        if (l == 0) sm[32] = r;
    }
    __syncthreads();
    float out = sm[32];
    __syncthreads();
    return out;
}

__device__ __forceinline__ float lrelu_scale_exp(float s) {
    float t = (s > 0.f) ? s : (ALPHA * s);
    return expf(t / SCALEF);
}

// ============ K_A: fold a^T.W prep + scan edge_out for src==N-1 ============
__global__ void kA(const int* __restrict__ eo,
                   const float* __restrict__ W1, const float* __restrict__ b1,
                   const float* __restrict__ a1,
                   const float* __restrict__ W2, const float* __restrict__ b2,
                   const float* __restrict__ a2) {
    int gid = blockIdx.x * blockDim.x + threadIdx.x;
    int stride = gridDim.x * blockDim.x;

    if (gid < 1024) {                       // u1/v1 = a1^T W1 (coalesced over k)
        int h = gid >> 8, k = gid & 255;
        float au = 0.f, av = 0.f;
#pragma unroll 8
        for (int j = 0; j < 128; j++) {
            float w = W1[(h * 128 + j) * 256 + k];
            au += a1[h * 256 + j] * w;
            av += a1[h * 256 + 128 + j] * w;
        }
        g_u1[h * 256 + k] = au;
        g_v1[h * 256 + k] = av;
    } else if (gid < 3072) {                // u2/v2 = a2^T W2
        int g2i = gid - 1024;
        int h = g2i >> 9, k = g2i & 511;
        float au = 0.f, av = 0.f;
#pragma unroll 8
        for (int j = 0; j < 128; j++) {
            float w = W2[(h * 128 + j) * 512 + k];
            au += a2[h * 256 + j] * w;
            av += a2[h * 256 + 128 + j] * w;
        }
        g_u2[h * 512 + k] = au;
        g_v2[h * 512 + k] = av;
    }
    if (gid < 4) {
        int h = gid;
        float c1v = 0.f, d1v = 0.f, c2v = 0.f, d2v = 0.f;
        for (int j = 0; j < 128; j++) {
            c1v += a1[h * 256 + j] * b1[h * 128 + j];
            d1v += a1[h * 256 + 128 + j] * b1[h * 128 + j];
            c2v += a2[h * 256 + j] * b2[h * 128 + j];
            d2v += a2[h * 256 + 128 + j] * b2[h * 128 + j];
        }
        g_c1s[h] = c1v; g_d1s[h] = d1v; g_c2s[h] = c2v; g_d2s[h] = d2v;
    }

    // vectorized scan of edge_out src rows
    const int NQ = NE / 4;
    for (int i = gid; i < NB * NQ; i += stride) {
        int b = (i >= NQ) ? 1 : 0;
        int e4 = i - b * NQ;
        int4 v = ((const int4*)(eo + (size_t)(2 * b) * NE))[e4];
        int base = e4 * 4;
#pragma unroll
        for (int c = 0; c < 4; c++) {
            int src = (c == 0) ? v.x : (c == 1) ? v.y : (c == 2) ? v.z : v.w;
            if (src == NN - 1) {
                int p = atomicAdd(&g_c2[b], 1);
                if (p < MAXL2)
                    g_l2dst[b * MAXL2 + p] = eo[(size_t)(2 * b + 1) * NE + base + c];
            }
        }
    }
}

// ============ K_B: dedupe dsts + node N-1, index the map ============
__global__ void kB() {
    int b = blockIdx.x, t = threadIdx.x;
    int cnt = min(g_c2[b], MAXL2);
    for (int i = t; i <= cnt; i += blockDim.x) {
        int node = (i == cnt) ? (NN - 1) : g_l2dst[b * MAXL2 + i];
        if (atomicCAS(&g_map[b * NN + node], 0, 1) == 0) {
            int p = atomicAdd(&g_nn[b], 1);
            g_nodes[b * MAXNODES + p] = node;
        }
    }
    __syncthreads();
    int nnr = g_nn[b];
    for (int i = t; i < nnr; i += blockDim.x)
        g_map[b * NN + g_nodes[b * MAXNODES + i]] = i + 1;
}

// ============ K_C: scan edge_in for src in node set ============
__global__ void kC(const int* __restrict__ ei) {
    int gid = blockIdx.x * blockDim.x + threadIdx.x;
    int stride = gridDim.x * blockDim.x;
    const int NQ = NE / 4;
    for (int i = gid; i < NB * NQ; i += stride) {
        int b = (i >= NQ) ? 1 : 0;
        int e4 = i - b * NQ;
        int4 v = ((const int4*)(ei + (size_t)(2 * b) * NE))[e4];
        int base = e4 * 4;
#pragma unroll
        for (int c = 0; c < 4; c++) {
            int src = (c == 0) ? v.x : (c == 1) ? v.y : (c == 2) ? v.z : v.w;
            int m = g_map[b * NN + src];
            if (m > 0) {
                int p = atomicAdd(&g_c1[b], 1);
                if (p < MAXE1) {
                    g_e1src[b * MAXE1 + p] = m - 1;
                    g_e1dst[b * MAXE1 + p] = ei[(size_t)(2 * b + 1) * NE + base + c];
                }
            }
        }
    }
}

// ============ K_D: layer-1, block-per-node, fused edge pass + projection =====
__global__ void __launch_bounds__(1024) kD(const float* __restrict__ embed,
                                           const float* __restrict__ W1,
                                           const float* __restrict__ b1,
                                           const float* __restrict__ g1,
                                           const float* __restrict__ bn1) {
    __shared__ int   s_dst[MAXEPN];
    __shared__ __align__(16) float s_agg[1024];
    __shared__ float s_out[512];
    __shared__ float s_x[256];
    __shared__ float s_sA[4];
    __shared__ float s_rs[4];
    __shared__ float s_red[33];
    __shared__ int   s_m;

    int b = blockIdx.x & 1, slot = blockIdx.x >> 1, nslots = gridDim.x >> 1;
    int t = threadIdx.x, lane = t & 31, w = t >> 5;
    int nnr = min(g_nn[b], MAXNODES);
    int cnt = min(g_c1[b], MAXE1);

    for (int ln = slot; ln < nnr; ln += nslots) {
        if (t == 0) s_m = 0;
        s_agg[t] = 0.f;
        if (t < 4) s_rs[t] = 0.f;
        __syncthreads();

        // collect this node's edges
        for (int i = t; i < cnt; i += 1024)
            if (g_e1src[b * MAXE1 + i] == ln) {
                int p = atomicAdd(&s_m, 1);
                if (p < MAXEPN) s_dst[p] = g_e1dst[b * MAXE1 + i];
            }
        int node = g_nodes[b * MAXNODES + ln];
        if (t < 256) s_x[t] = embed[(size_t)node * 256 + t];
        __syncthreads();
        int m = min(s_m, MAXEPN);

        // sA1[h] = emb[node].u1[h] + c1s[h]  (warp per head)
        if (w < 4) {
            float a = 0.f;
#pragma unroll
            for (int q = 0; q < 8; q++) a += s_x[lane + 32 * q] * g_u1[w * 256 + lane + 32 * q];
            a = warp_sum(a);
            if (lane == 0) s_sA[w] = a + g_c1s[w];
        }
        __syncthreads();

        // fused attention + aggregation: warp per edge, register partials
        {
            float acc[4][8];
            float rsacc[4] = {0.f, 0.f, 0.f, 0.f};
#pragma unroll
            for (int h = 0; h < 4; h++)
#pragma unroll
                for (int q = 0; q < 8; q++) acc[h][q] = 0.f;
            for (int e = w; e < m; e += 32) {
                const float* er = embed + (size_t)s_dst[e] * 256;
                float emb[8];
#pragma unroll
                for (int q = 0; q < 8; q++) emb[q] = er[lane + 32 * q];
#pragma unroll
                for (int h = 0; h < 4; h++) {
                    float a = 0.f;
#pragma unroll
                    for (int q = 0; q < 8; q++) a += emb[q] * g_v1[h * 256 + lane + 32 * q];
                    a = warp_sum(a);  // full sum on all lanes
                    float ev = lrelu_scale_exp(s_sA[h] + a + g_d1s[h]);
                    rsacc[h] += ev;
#pragma unroll
                    for (int q = 0; q < 8; q++) acc[h][q] += ev * emb[q];
                }
            }
#pragma unroll
            for (int h = 0; h < 4; h++) {
#pragma unroll
                for (int q = 0; q < 8; q++)
                    atomicAdd(&s_agg[h * 256 + lane + 32 * q], acc[h][q]);
                if (lane == 0) atomicAdd(&s_rs[h], rsacc[h]);
            }
        }
        __syncthreads();

        // projection: warp per row, 16 rows/warp, unrolled for MLP
#pragma unroll
        for (int i = 0; i < 16; i++) {
            int r = w + 32 * i;
            int h = r >> 7;
            const float4* wr = (const float4*)(W1 + (size_t)r * 256);
            const float4* ag = (const float4*)(s_agg + h * 256);
            float4 w0 = wr[lane], w1 = wr[lane + 32];
            float4 a0 = ag[lane], a1 = ag[lane + 32];
            float acc = w0.x * a0.x + w0.y * a0.y + w0.z * a0.z + w0.w * a0.w
                      + w1.x * a1.x + w1.y * a1.y + w1.z * a1.z + w1.w * a1.w;
            acc = warp_sum(acc);
            if (lane == 0) {
                float rs = s_rs[h];
                float rsp = (rs == 0.f) ? 1.f : rs;
                s_out[r] = (acc + rs * b1[r]) / rsp;
            }
        }
        __syncthreads();

        // layernorm(512, ddof=1, eps on std) + elu
        float val = (t < 512) ? s_out[t] : 0.f;
        float tot = block_sum(val, s_red);
        float mn = tot * (1.f / 512.f);
        float dv = (t < 512) ? (val - mn) : 0.f;
        float sq = block_sum(dv * dv, s_red);
        float stdv = sqrtf(sq * (1.f / 511.f));
        if (t < 512) {
            float y = g1[t] * dv / (stdv + LN_EPS) + bn1[t];
            g_hcat[((size_t)b * MAXNODES + ln) * 512 + t] = (y > 0.f) ? y : expm1f(y);
        }
        __syncthreads();
    }
}

// ============ K_E: layer-2 + final head, block-per-batch + cleanup ===========
__global__ void __launch_bounds__(1024) kE(const float* __restrict__ W2,
                                           const float* __restrict__ b2,
                                           const float* __restrict__ g2,
                                           const float* __restrict__ bn2,
                                           const float* __restrict__ Vw,
                                           const float* __restrict__ Vb,
                                           float* __restrict__ out) {
    __shared__ int   s_ln[MAXL2];
    __shared__ __align__(16) float s_agg[2048];
    __shared__ float s_p[512];
    __shared__ float s_x[512];
    __shared__ float s_sA[4];
    __shared__ float s_rs[4];
    __shared__ float s_red[33];

    int b = blockIdx.x;
    int t = threadIdx.x, lane = t & 31, w = t >> 5;
    int cnt = min(g_c2[b], MAXL2);
    int ln0 = g_map[b * NN + (NN - 1)] - 1;
    if (ln0 < 0) ln0 = 0;

    if (t < 512) s_x[t] = g_hcat[((size_t)b * MAXNODES + ln0) * 512 + t];
    s_agg[t] = 0.f; s_agg[t + 1024] = 0.f;
    if (t < 4) s_rs[t] = 0.f;
    for (int i = t; i < cnt; i += 1024)
        s_ln[i] = g_map[b * NN + g_l2dst[b * MAXL2 + i]] - 1;
    __syncthreads();

    if (w < 4) {
        float a = 0.f;
#pragma unroll
        for (int q = 0; q < 16; q++) a += s_x[lane + 32 * q] * g_u2[w * 512 + lane + 32 * q];
        a = warp_sum(a);
        if (lane == 0) s_sA[w] = a + g_c2s[w];
    }
    __syncthreads();

    // fused attention + aggregation: warp handles (edge, head) units; h fixed per warp
    {
        int h = w & 3;
        float acc[16];
        float rsacc = 0.f;
#pragma unroll
        for (int q = 0; q < 16; q++) acc[q] = 0.f;
        for (int e = (w >> 2); e < cnt; e += 8) {
            const float* hr = g_hcat + ((size_t)b * MAXNODES + s_ln[e]) * 512;
            float hv[16];
#pragma unroll
            for (int q = 0; q < 16; q++) hv[q] = hr[lane + 32 * q];
            float a = 0.f;
#pragma unroll
            for (int q = 0; q < 16; q++) a += hv[q] * g_v2[h * 512 + lane + 32 * q];
            a = warp_sum(a);
            float ev = lrelu_scale_exp(s_sA[h] + a + g_d2s[h]);
            rsacc += ev;
#pragma unroll
            for (int q = 0; q < 16; q++) acc[q] += ev * hv[q];
        }
#pragma unroll
        for (int q = 0; q < 16; q++)
            atomicAdd(&s_agg[h * 512 + lane + 32 * q], acc[q]);
        if (lane == 0) atomicAdd(&s_rs[h], rsacc);
    }
    __syncthreads();

    // projection: warp per row, 16 rows/warp
#pragma unroll
    for (int i = 0; i < 16; i++) {
        int r = w + 32 * i;
        int h = r >> 7;
        const float4* wr = (const float4*)(W2 + (size_t)r * 512);
        const float4* ag = (const float4*)(s_agg + h * 512);
        float a = 0.f;
#pragma unroll
        for (int q = 0; q < 4; q++) {
            float4 wv = wr[lane + 32 * q];
            float4 av = ag[lane + 32 * q];
            a += wv.x * av.x + wv.y * av.y + wv.z * av.z + wv.w * av.w;
        }
        a = warp_sum(a);
        if (lane == 0) {
            float rs = s_rs[h];
            float rsp = (rs == 0.f) ? 1.f : rs;
            s_p[r] = (a + rs * b2[r]) / rsp;
        }
    }
    __syncthreads();

    // mean over heads, layernorm(128, ddof=1), relu, final 128->2
    float v = 0.f;
    if (t < 128) v = 0.25f * (s_p[t] + s_p[128 + t] + s_p[256 + t] + s_p[384 + t]);
    float tot = block_sum((t < 128) ? v : 0.f, s_red);
    float mn = tot * (1.f / 128.f);
    float dv = (t < 128) ? (v - mn) : 0.f;
    float sq = block_sum(dv * dv, s_red);
    float stdv = sqrtf(sq * (1.f / 127.f));
    float r0 = 0.f, r1 = 0.f;
    if (t < 128) {
        float y = g2[t] * dv / (stdv + LN_EPS) + bn2[t];
        float rr = (y > 0.f) ? y : 0.f;
        r0 = rr * Vw[t];
        r1 = rr * Vw[128 + t];
    }
    float o0 = block_sum(r0, s_red);
    float o1 = block_sum(r1, s_red);
    if (t == 0) {
        out[b * 2 + 0] = o0 + Vb[0];
        out[b * 2 + 1] = o1 + Vb[1];
    }

    // self-cleaning for next replay
    __syncthreads();
    int nnr = min(g_nn[b], MAXNODES);
    for (int i = t; i < nnr; i += 1024) g_map[b * NN + g_nodes[b * MAXNODES + i]] = 0;
    if (t == 0) { g_nn[b] = 0; g_c1[b] = 0; g_c2[b] = 0; }
}

// ---------------- launch ----------------
extern "C" void kernel_launch(void* const* d_in, const int* in_sizes, int n_in,
                              void* d_out, int out_size) {
    const int* edge_in = (const int*)d_in[0];
    const int* edge_out = (const int*)d_in[1];
    const float* embed = (const float*)d_in[2];
    const float* W1 = (const float*)d_in[3];
    const float* b1 = (const float*)d_in[4];
    const float* a1 = (const float*)d_in[5];
    const float* g1 = (const float*)d_in[6];
    const float* bn1 = (const float*)d_in[7];
    const float* W2 = (const float*)d_in[8];
    const float* b2 = (const float*)d_in[9];
    const float* a2 = (const float*)d_in[10];
    const float* g2 = (const float*)d_in[11];
    const float* bn2 = (const float*)d_in[12];
    const float* Vw = (const float*)d_in[13];
    const float* Vb = (const float*)d_in[14];
    float* out = (float*)d_out;

    kA<<<512, 256>>>(edge_out, W1, b1, a1, W2, b2, a2);
    kB<<<NB, 256>>>();
    kC<<<512, 256>>>(edge_in);
    kD<<<64, 1024>>>(embed, W1, b1, g1, bn1);
    kE<<<NB, 1024>>>(W2, b2, g2, bn2, Vw, Vb, out);
}

// round 4
// speedup vs baseline: 4.2547x; 1.0096x over previous
#include <cuda_runtime.h>
#include <math.h>

#define NB 2
#define NN 20001
#define NE 500000
#define MAXL2 4096
#define MAXNODES (MAXL2 + 1)
#define MAXE1 65536
#define MAXEPN 1024
#define CH2 1024
#define SCALEF 22.62741699796952f
#define INV_SCALEF (1.0f / 22.62741699796952f)
#define LN_EPS 1e-6f
#define ALPHA 0.2f

// ---------------- scratch (device globals; zero-init on load) ----------------
__device__ int   g_map[NB * NN];          // 0 = absent, else local_idx+1
__device__ int   g_nodes[NB * MAXNODES];
__device__ int   g_nn[NB];
__device__ int   g_c1[NB];
__device__ int   g_c2[NB];
__device__ int   g_done;
__device__ int   g_l2dst[NB * MAXL2];
__device__ int   g_e1src[NB * MAXE1];
__device__ int   g_e1dst[NB * MAXE1];
__device__ float g_u1[4 * 256], g_v1[4 * 256], g_c1s[4], g_d1s[4];
__device__ float g_u2[4 * 512], g_v2[4 * 512], g_c2s[4], g_d2s[4];
__device__ float g_hcat[(size_t)NB * MAXNODES * 512];

// ---------------- helpers ----------------
__device__ __forceinline__ float warp_sum(float v) {
#pragma unroll
    for (int o = 16; o > 0; o >>= 1) v += __shfl_xor_sync(0xffffffffu, v, o);
    return v;
}

__device__ float block_sum(float v, float* sm) {
    int tid = threadIdx.x, w = tid >> 5, l = tid & 31, nw = blockDim.x >> 5;
    v = warp_sum(v);
    if (l == 0) sm[w] = v;
    __syncthreads();
    if (w == 0) {
        float r = (l < nw) ? sm[l] : 0.f;
        r = warp_sum(r);
        if (l == 0) sm[32] = r;
    }
    __syncthreads();
    float out = sm[32];
    __syncthreads();
    return out;
}

__device__ __forceinline__ float lrelu_scale_exp(float s) {
    float t = (s > 0.f) ? s : (ALPHA * s);
    return __expf(t * INV_SCALEF);
}

// ===== K_A: prep (a^T.W folds) + scan edge_out + tail-block dedupe/index =====
__global__ void kA(const int* __restrict__ eo,
                   const float* __restrict__ W1, const float* __restrict__ b1,
                   const float* __restrict__ a1,
                   const float* __restrict__ W2, const float* __restrict__ b2,
                   const float* __restrict__ a2) {
    __shared__ int s_last;
    int gid = blockIdx.x * blockDim.x + threadIdx.x;
    int stride = gridDim.x * blockDim.x;

    if (gid < 1024) {                       // u1/v1 = a1^T W1 (coalesced over k)
        int h = gid >> 8, k = gid & 255;
        float au = 0.f, av = 0.f;
#pragma unroll 8
        for (int j = 0; j < 128; j++) {
            float w = W1[(h * 128 + j) * 256 + k];
            au += a1[h * 256 + j] * w;
            av += a1[h * 256 + 128 + j] * w;
        }
        g_u1[h * 256 + k] = au;
        g_v1[h * 256 + k] = av;
    } else if (gid < 3072) {                // u2/v2 = a2^T W2
        int g2i = gid - 1024;
        int h = g2i >> 9, k = g2i & 511;
        float au = 0.f, av = 0.f;
#pragma unroll 8
        for (int j = 0; j < 128; j++) {
            float w = W2[(h * 128 + j) * 512 + k];
            au += a2[h * 256 + j] * w;
            av += a2[h * 256 + 128 + j] * w;
        }
        g_u2[h * 512 + k] = au;
        g_v2[h * 512 + k] = av;
    }
    if (gid < 4) {
        int h = gid;
        float c1v = 0.f, d1v = 0.f, c2v = 0.f, d2v = 0.f;
        for (int j = 0; j < 128; j++) {
            c1v += a1[h * 256 + j] * b1[h * 128 + j];
            d1v += a1[h * 256 + 128 + j] * b1[h * 128 + j];
            c2v += a2[h * 256 + j] * b2[h * 128 + j];
            d2v += a2[h * 256 + 128 + j] * b2[h * 128 + j];
        }
        g_c1s[h] = c1v; g_d1s[h] = d1v; g_c2s[h] = c2v; g_d2s[h] = d2v;
    }

    // vectorized scan of edge_out src rows
    const int NQ = NE / 4;
    for (int i = gid; i < NB * NQ; i += stride) {
        int b = (i >= NQ) ? 1 : 0;
        int e4 = i - b * NQ;
        int4 v = ((const int4*)(eo + (size_t)(2 * b) * NE))[e4];
        int base = e4 * 4;
#pragma unroll
        for (int c = 0; c < 4; c++) {
            int src = (c == 0) ? v.x : (c == 1) ? v.y : (c == 2) ? v.z : v.w;
            if (src == NN - 1) {
                int p = atomicAdd(&g_c2[b], 1);
                if (p < MAXL2)
                    g_l2dst[b * MAXL2 + p] = eo[(size_t)(2 * b + 1) * NE + base + c];
            }
        }
    }

    // last block to finish performs the dedupe + map indexing (was kB)
    __threadfence();
    if (threadIdx.x == 0) s_last = (atomicAdd(&g_done, 1) == (int)gridDim.x - 1);
    __syncthreads();
    if (s_last) {
        __threadfence();
        int t = threadIdx.x;
        for (int b = 0; b < NB; b++) {
            int cnt = min(g_c2[b], MAXL2);
            for (int i = t; i <= cnt; i += blockDim.x) {
                int node = (i == cnt) ? (NN - 1) : g_l2dst[b * MAXL2 + i];
                if (atomicCAS(&g_map[b * NN + node], 0, 1) == 0) {
                    int p = atomicAdd(&g_nn[b], 1);
                    g_nodes[b * MAXNODES + p] = node;
                }
            }
            __syncthreads();
            int nnr = g_nn[b];
            for (int i = t; i < nnr; i += blockDim.x)
                g_map[b * NN + g_nodes[b * MAXNODES + i]] = i + 1;
            __syncthreads();
        }
    }
}

// ============ K_C: scan edge_in for src in node set ============
__global__ void kC(const int* __restrict__ ei) {
    int gid = blockIdx.x * blockDim.x + threadIdx.x;
    int stride = gridDim.x * blockDim.x;
    const int NQ = NE / 4;
    for (int i = gid; i < NB * NQ; i += stride) {
        int b = (i >= NQ) ? 1 : 0;
        int e4 = i - b * NQ;
        int4 v = ((const int4*)(ei + (size_t)(2 * b) * NE))[e4];
        int base = e4 * 4;
#pragma unroll
        for (int c = 0; c < 4; c++) {
            int src = (c == 0) ? v.x : (c == 1) ? v.y : (c == 2) ? v.z : v.w;
            int m = g_map[b * NN + src];
            if (m > 0) {
                int p = atomicAdd(&g_c1[b], 1);
                if (p < MAXE1) {
                    g_e1src[b * MAXE1 + p] = m - 1;
                    g_e1dst[b * MAXE1 + p] = ei[(size_t)(2 * b + 1) * NE + base + c];
                }
            }
        }
    }
}

// ===== K_D: layer-1, block-per-node, two-pass (NO aggregation atomics) =======
__global__ void __launch_bounds__(1024) kD(const float* __restrict__ embed,
                                           const float* __restrict__ W1,
                                           const float* __restrict__ b1,
                                           const float* __restrict__ g1,
                                           const float* __restrict__ bn1) {
    __shared__ int   s_dst[MAXEPN];
    __shared__ float s_ev[MAXEPN * 4];
    __shared__ __align__(16) float s_agg[1024];
    __shared__ float s_out[512];
    __shared__ float s_x[256];
    __shared__ float s_sA[4];
    __shared__ float s_rs[4];
    __shared__ float s_red[33];
    __shared__ int   s_m;

    int b = blockIdx.x & 1, slot = blockIdx.x >> 1, nslots = gridDim.x >> 1;
    int t = threadIdx.x, lane = t & 31, w = t >> 5;
    int nnr = min(g_nn[b], MAXNODES);
    int cnt = min(g_c1[b], MAXE1);

    for (int ln = slot; ln < nnr; ln += nslots) {
        if (t == 0) s_m = 0;
        __syncthreads();

        // collect this node's edges
        for (int i = t; i < cnt; i += 1024)
            if (g_e1src[b * MAXE1 + i] == ln) {
                int p = atomicAdd(&s_m, 1);
                if (p < MAXEPN) s_dst[p] = g_e1dst[b * MAXE1 + i];
            }
        int node = g_nodes[b * MAXNODES + ln];
        if (t < 256) s_x[t] = embed[(size_t)node * 256 + t];
        __syncthreads();
        int m = min(s_m, MAXEPN);

        // sA1[h] = emb[node].u1[h] + c1s[h]  (warp per head)
        if (w < 4) {
            float a = 0.f;
#pragma unroll
            for (int q = 0; q < 8; q++) a += s_x[lane + 32 * q] * g_u1[w * 256 + lane + 32 * q];
            a = warp_sum(a);
            if (lane == 0) s_sA[w] = a + g_c1s[w];
        }
        __syncthreads();

        // pass 1: warp per edge -> attention weights only (ILP'd butterflies)
        for (int e = w; e < m; e += 32) {
            const float* er = embed + (size_t)s_dst[e] * 256;
            float emb[8];
#pragma unroll
            for (int q = 0; q < 8; q++) emb[q] = er[lane + 32 * q];
            float a4[4];
#pragma unroll
            for (int h = 0; h < 4; h++) {
                float a = 0.f;
#pragma unroll
                for (int q = 0; q < 8; q++) a += emb[q] * g_v1[h * 256 + lane + 32 * q];
                a4[h] = a;
            }
#pragma unroll
            for (int o = 16; o > 0; o >>= 1) {
#pragma unroll
                for (int h = 0; h < 4; h++) a4[h] += __shfl_xor_sync(0xffffffffu, a4[h], o);
            }
            float sel = (lane == 0) ? a4[0] : (lane == 1) ? a4[1] : (lane == 2) ? a4[2] : a4[3];
            if (lane < 4) s_ev[e * 4 + lane] = lrelu_scale_exp(s_sA[lane] + sel + g_d1s[lane]);
        }
        __syncthreads();

        // pass 2: threads 0-255 feature-parallel aggregation; warps 28-31 rowsums
        if (t < 256) {
            float a0 = 0.f, a1v = 0.f, a2v = 0.f, a3v = 0.f;
#pragma unroll 4
            for (int e = 0; e < m; e++) {
                float x = embed[(size_t)s_dst[e] * 256 + t];
                a0  += s_ev[e * 4 + 0] * x;
                a1v += s_ev[e * 4 + 1] * x;
                a2v += s_ev[e * 4 + 2] * x;
                a3v += s_ev[e * 4 + 3] * x;
            }
            s_agg[0 * 256 + t] = a0;
            s_agg[1 * 256 + t] = a1v;
            s_agg[2 * 256 + t] = a2v;
            s_agg[3 * 256 + t] = a3v;
        } else if (w >= 28) {
            int h = w - 28;
            float r = 0.f;
            for (int e = lane; e < m; e += 32) r += s_ev[e * 4 + h];
            r = warp_sum(r);
            if (lane == 0) s_rs[h] = r;
        }
        __syncthreads();

        // projection: warp per row, 16 rows/warp, float4 coalesced
#pragma unroll
        for (int i = 0; i < 16; i++) {
            int r = w + 32 * i;
            int h = r >> 7;
            const float4* wr = (const float4*)(W1 + (size_t)r * 256);
            const float4* ag = (const float4*)(s_agg + h * 256);
            float4 w0 = wr[lane], w1 = wr[lane + 32];
            float4 a0 = ag[lane], a1 = ag[lane + 32];
            float acc = w0.x * a0.x + w0.y * a0.y + w0.z * a0.z + w0.w * a0.w
                      + w1.x * a1.x + w1.y * a1.y + w1.z * a1.z + w1.w * a1.w;
            acc = warp_sum(acc);
            if (lane == 0) {
                float rs = s_rs[h];
                float rsp = (rs == 0.f) ? 1.f : rs;
                s_out[r] = (acc + rs * b1[r]) / rsp;
            }
        }
        __syncthreads();

        // layernorm(512, ddof=1, eps on std) + elu
        float val = (t < 512) ? s_out[t] : 0.f;
        float tot = block_sum(val, s_red);
        float mn = tot * (1.f / 512.f);
        float dv = (t < 512) ? (val - mn) : 0.f;
        float sq = block_sum(dv * dv, s_red);
        float stdv = sqrtf(sq * (1.f / 511.f));
        if (t < 512) {
            float y = g1[t] * dv / (stdv + LN_EPS) + bn1[t];
            g_hcat[((size_t)b * MAXNODES + ln) * 512 + t] = (y > 0.f) ? y : expm1f(y);
        }
        __syncthreads();
    }
}

// ===== K_E: layer-2 + head, block-per-batch, two-pass, + cleanup =============
__global__ void __launch_bounds__(1024) kE(const float* __restrict__ W2,
                                           const float* __restrict__ b2,
                                           const float* __restrict__ g2,
                                           const float* __restrict__ bn2,
                                           const float* __restrict__ Vw,
                                           const float* __restrict__ Vb,
                                           float* __restrict__ out) {
    __shared__ int   s_ln[CH2];
    __shared__ float s_ev[CH2 * 4];
    __shared__ __align__(16) float s_agg[2048];
    __shared__ float s_p[512];
    __shared__ float s_x[512];
    __shared__ float s_sA[4];
    __shared__ float s_rs[4];
    __shared__ float s_red[33];

    int b = blockIdx.x;
    int t = threadIdx.x, lane = t & 31, w = t >> 5;
    int cnt = min(g_c2[b], MAXL2);
    int ln0 = g_map[b * NN + (NN - 1)] - 1;
    if (ln0 < 0) ln0 = 0;

    if (t < 512) s_x[t] = g_hcat[((size_t)b * MAXNODES + ln0) * 512 + t];
    if (t < 4) s_rs[t] = 0.f;
    __syncthreads();

    if (w < 4) {
        float a = 0.f;
#pragma unroll
        for (int q = 0; q < 16; q++) a += s_x[lane + 32 * q] * g_u2[w * 512 + lane + 32 * q];
        a = warp_sum(a);
        if (lane == 0) s_sA[w] = a + g_c2s[w];
    }
    __syncthreads();

    float c0 = 0.f, c1v = 0.f, c2v = 0.f, c3v = 0.f;   // per-c accumulators (t<512)
    for (int base = 0; base < cnt; base += CH2) {
        int mc = min(cnt - base, CH2);
        for (int e = t; e < mc; e += 1024)
            s_ln[e] = g_map[b * NN + g_l2dst[b * MAXL2 + base + e]] - 1;
        __syncthreads();

        // pass 1: warp per edge -> attention weights
        for (int e = w; e < mc; e += 32) {
            const float* hr = g_hcat + ((size_t)b * MAXNODES + s_ln[e]) * 512;
            float hv[16];
#pragma unroll
            for (int q = 0; q < 16; q++) hv[q] = hr[lane + 32 * q];
            float a4[4];
#pragma unroll
            for (int h = 0; h < 4; h++) {
                float a = 0.f;
#pragma unroll
                for (int q = 0; q < 16; q++) a += hv[q] * g_v2[h * 512 + lane + 32 * q];
                a4[h] = a;
            }
#pragma unroll
            for (int o = 16; o > 0; o >>= 1) {
#pragma unroll
                for (int h = 0; h < 4; h++) a4[h] += __shfl_xor_sync(0xffffffffu, a4[h], o);
            }
            float sel = (lane == 0) ? a4[0] : (lane == 1) ? a4[1] : (lane == 2) ? a4[2] : a4[3];
            if (lane < 4) s_ev[e * 4 + lane] = lrelu_scale_exp(s_sA[lane] + sel + g_d2s[lane]);
        }
        __syncthreads();

        // pass 2: threads 0-511 feature-parallel aggregation; warps 28-31 rowsums
        if (t < 512) {
#pragma unroll 4
            for (int e = 0; e < mc; e++) {
                float x = g_hcat[((size_t)b * MAXNODES + s_ln[e]) * 512 + t];
                c0  += s_ev[e * 4 + 0] * x;
                c1v += s_ev[e * 4 + 1] * x;
                c2v += s_ev[e * 4 + 2] * x;
                c3v += s_ev[e * 4 + 3] * x;
            }
        } else if (w >= 28) {
            int h = w - 28;
            float r = 0.f;
            for (int e = lane; e < mc; e += 32) r += s_ev[e * 4 + h];
            r = warp_sum(r);
            if (lane == 0) s_rs[h] += r;
        }
        __syncthreads();
    }
    if (t < 512) {
        s_agg[0 * 512 + t] = c0;
        s_agg[1 * 512 + t] = c1v;
        s_agg[2 * 512 + t] = c2v;
        s_agg[3 * 512 + t] = c3v;
    }
    __syncthreads();

    // projection: warp per row, 16 rows/warp
#pragma unroll
    for (int i = 0; i < 16; i++) {
        int r = w + 32 * i;
        int h = r >> 7;
        const float4* wr = (const float4*)(W2 + (size_t)r * 512);
        const float4* ag = (const float4*)(s_agg + h * 512);
        float a = 0.f;
#pragma unroll
        for (int q = 0; q < 4; q++) {
            float4 wv = wr[lane + 32 * q];
            float4 av = ag[lane + 32 * q];
            a += wv.x * av.x + wv.y * av.y + wv.z * av.z + wv.w * av.w;
        }
        a = warp_sum(a);
        if (lane == 0) {
            float rs = s_rs[h];
            float rsp = (rs == 0.f) ? 1.f : rs;
            s_p[r] = (a + rs * b2[r]) / rsp;
        }
    }
    __syncthreads();

    // mean over heads, layernorm(128, ddof=1), relu, final 128->2
    float v = 0.f;
    if (t < 128) v = 0.25f * (s_p[t] + s_p[128 + t] + s_p[256 + t] + s_p[384 + t]);
    float tot = block_sum((t < 128) ? v : 0.f, s_red);
    float mn = tot * (1.f / 128.f);
    float dv = (t < 128) ? (v - mn) : 0.f;
    float sq = block_sum(dv * dv, s_red);
    float stdv = sqrtf(sq * (1.f / 127.f));
    float r0 = 0.f, r1 = 0.f;
    if (t < 128) {
        float y = g2[t] * dv / (stdv + LN_EPS) + bn2[t];
        float rr = (y > 0.f) ? y : 0.f;
        r0 = rr * Vw[t];
        r1 = rr * Vw[128 + t];
    }
    float o0 = block_sum(r0, s_red);
    float o1 = block_sum(r1, s_red);
    if (t == 0) {
        out[b * 2 + 0] = o0 + Vb[0];
        out[b * 2 + 1] = o1 + Vb[1];
    }

    // self-cleaning for next replay
    __syncthreads();
    int nnr = min(g_nn[b], MAXNODES);
    for (int i = t; i < nnr; i += 1024) g_map[b * NN + g_nodes[b * MAXNODES + i]] = 0;
    if (t == 0) { g_nn[b] = 0; g_c1[b] = 0; g_c2[b] = 0; if (b == 0) g_done = 0; }
}

// ---------------- launch ----------------
extern "C" void kernel_launch(void* const* d_in, const int* in_sizes, int n_in,
                              void* d_out, int out_size) {
    const int* edge_in = (const int*)d_in[0];
    const int* edge_out = (const int*)d_in[1];
    const float* embed = (const float*)d_in[2];
    const float* W1 = (const float*)d_in[3];
    const float* b1 = (const float*)d_in[4];
    const float* a1 = (const float*)d_in[5];
    const float* g1 = (const float*)d_in[6];
    const float* bn1 = (const float*)d_in[7];
    const float* W2 = (const float*)d_in[8];
    const float* b2 = (const float*)d_in[9];
    const float* a2 = (const float*)d_in[10];
    const float* g2 = (const float*)d_in[11];
    const float* bn2 = (const float*)d_in[12];
    const float* Vw = (const float*)d_in[13];
    const float* Vb = (const float*)d_in[14];
    float* out = (float*)d_out;

    kA<<<512, 256>>>(edge_out, W1, b1, a1, W2, b2, a2);
    kC<<<512, 256>>>(edge_in);
    kD<<<64, 1024>>>(embed, W1, b1, g1, bn1);
    kE<<<NB, 1024>>>(W2, b2, g2, bn2, Vw, Vb, out);
}

// round 5
// speedup vs baseline: 4.6091x; 1.0833x over previous
#include <cuda_runtime.h>
#include <math.h>

#define NB 2
#define NN 20001
#define NE 500000
#define MAXL2 4096
#define MAXNODES (MAXL2 + 1)
#define MAXE1 65536
#define MAXEPN 1024
#define CH2 1024
#define SCALEF 22.62741699796952f
#define INV_SCALEF (1.0f / 22.62741699796952f)
#define LN_EPS 1e-6f
#define ALPHA 0.2f

// ---------------- scratch (device globals; zero-init on load) ----------------
__device__ int   g_map[NB * NN];          // 0 = absent, else local_idx+1
__device__ int   g_nodes[NB * MAXNODES];
__device__ int   g_nn[NB];
__device__ int   g_c1[NB];
__device__ int   g_c2[NB];
__device__ int   g_done;
__device__ int   g_done2[NB];
__device__ int   g_l2dst[NB * MAXL2];
__device__ int   g_e1src[NB * MAXE1];
__device__ int   g_e1dst[NB * MAXE1];
__device__ float g_u1[4 * 256], g_v1[4 * 256], g_c1s[4], g_d1s[4];
__device__ float g_u2[4 * 512], g_v2[4 * 512], g_c2s[4], g_d2s[4];
__device__ float g_hcat[(size_t)NB * MAXNODES * 512];
__device__ __align__(16) float g_agg2[NB * 2048];
__device__ float g_rs2[NB * 4];
__device__ float g_p[NB * 512];

// ---------------- helpers ----------------
__device__ __forceinline__ float warp_sum(float v) {
#pragma unroll
    for (int o = 16; o > 0; o >>= 1) v += __shfl_xor_sync(0xffffffffu, v, o);
    return v;
}

__device__ float block_sum(float v, float* sm) {
    int tid = threadIdx.x, w = tid >> 5, l = tid & 31, nw = blockDim.x >> 5;
    v = warp_sum(v);
    if (l == 0) sm[w] = v;
    __syncthreads();
    if (w == 0) {
        float r = (l < nw) ? sm[l] : 0.f;
        r = warp_sum(r);
        if (l == 0) sm[32] = r;
    }
    __syncthreads();
    float out = sm[32];
    __syncthreads();
    return out;
}

__device__ __forceinline__ float lrelu_scale_exp(float s) {
    float t = (s > 0.f) ? s : (ALPHA * s);
    return __expf(t * INV_SCALEF);
}

// ===== K_A: prep (a^T.W folds) + scan edge_out + tail-block dedupe/index =====
__global__ void kA(const int* __restrict__ eo,
                   const float* __restrict__ W1, const float* __restrict__ b1,
                   const float* __restrict__ a1,
                   const float* __restrict__ W2, const float* __restrict__ b2,
                   const float* __restrict__ a2) {
    __shared__ int s_last;
    int gid = blockIdx.x * blockDim.x + threadIdx.x;
    int stride = gridDim.x * blockDim.x;

    if (gid < 1024) {                       // u1/v1 = a1^T W1 (coalesced over k)
        int h = gid >> 8, k = gid & 255;
        float au = 0.f, av = 0.f;
#pragma unroll 8
        for (int j = 0; j < 128; j++) {
            float w = W1[(h * 128 + j) * 256 + k];
            au += a1[h * 256 + j] * w;
            av += a1[h * 256 + 128 + j] * w;
        }
        g_u1[h * 256 + k] = au;
        g_v1[h * 256 + k] = av;
    } else if (gid < 3072) {                // u2/v2 = a2^T W2
        int g2i = gid - 1024;
        int h = g2i >> 9, k = g2i & 511;
        float au = 0.f, av = 0.f;
#pragma unroll 8
        for (int j = 0; j < 128; j++) {
            float w = W2[(h * 128 + j) * 512 + k];
            au += a2[h * 256 + j] * w;
            av += a2[h * 256 + 128 + j] * w;
        }
        g_u2[h * 512 + k] = au;
        g_v2[h * 512 + k] = av;
    }
    if (gid < 4) {
        int h = gid;
        float c1v = 0.f, d1v = 0.f, c2v = 0.f, d2v = 0.f;
        for (int j = 0; j < 128; j++) {
            c1v += a1[h * 256 + j] * b1[h * 128 + j];
            d1v += a1[h * 256 + 128 + j] * b1[h * 128 + j];
            c2v += a2[h * 256 + j] * b2[h * 128 + j];
            d2v += a2[h * 256 + 128 + j] * b2[h * 128 + j];
        }
        g_c1s[h] = c1v; g_d1s[h] = d1v; g_c2s[h] = c2v; g_d2s[h] = d2v;
    }

    // vectorized scan of edge_out src rows
    const int NQ = NE / 4;
    for (int i = gid; i < NB * NQ; i += stride) {
        int b = (i >= NQ) ? 1 : 0;
        int e4 = i - b * NQ;
        int4 v = ((const int4*)(eo + (size_t)(2 * b) * NE))[e4];
        int base = e4 * 4;
#pragma unroll
        for (int c = 0; c < 4; c++) {
            int src = (c == 0) ? v.x : (c == 1) ? v.y : (c == 2) ? v.z : v.w;
            if (src == NN - 1) {
                int p = atomicAdd(&g_c2[b], 1);
                if (p < MAXL2)
                    g_l2dst[b * MAXL2 + p] = eo[(size_t)(2 * b + 1) * NE + base + c];
            }
        }
    }

    // last block to finish performs the dedupe + map indexing
    __threadfence();
    if (threadIdx.x == 0) s_last = (atomicAdd(&g_done, 1) == (int)gridDim.x - 1);
    __syncthreads();
    if (s_last) {
        __threadfence();
        int t = threadIdx.x;
        for (int b = 0; b < NB; b++) {
            int cnt = min(g_c2[b], MAXL2);
            for (int i = t; i <= cnt; i += blockDim.x) {
                int node = (i == cnt) ? (NN - 1) : g_l2dst[b * MAXL2 + i];
                if (atomicCAS(&g_map[b * NN + node], 0, 1) == 0) {
                    int p = atomicAdd(&g_nn[b], 1);
                    g_nodes[b * MAXNODES + p] = node;
                }
            }
            __syncthreads();
            int nnr = g_nn[b];
            for (int i = t; i < nnr; i += blockDim.x)
                g_map[b * NN + g_nodes[b * MAXNODES + i]] = i + 1;
            __syncthreads();
        }
    }
}

// ============ K_C: scan edge_in for src in node set ============
__global__ void kC(const int* __restrict__ ei) {
    int gid = blockIdx.x * blockDim.x + threadIdx.x;
    int stride = gridDim.x * blockDim.x;
    const int NQ = NE / 4;
    for (int i = gid; i < NB * NQ; i += stride) {
        int b = (i >= NQ) ? 1 : 0;
        int e4 = i - b * NQ;
        int4 v = ((const int4*)(ei + (size_t)(2 * b) * NE))[e4];
        int base = e4 * 4;
#pragma unroll
        for (int c = 0; c < 4; c++) {
            int src = (c == 0) ? v.x : (c == 1) ? v.y : (c == 2) ? v.z : v.w;
            int m = g_map[b * NN + src];
            if (m > 0) {
                int p = atomicAdd(&g_c1[b], 1);
                if (p < MAXE1) {
                    g_e1src[b * MAXE1 + p] = m - 1;
                    g_e1dst[b * MAXE1 + p] = ei[(size_t)(2 * b + 1) * NE + base + c];
                }
            }
        }
    }
}

// ===== K_D: layer-1, block-per-node, two-pass (no aggregation atomics) =======
__global__ void __launch_bounds__(1024) kD(const float* __restrict__ embed,
                                           const float* __restrict__ W1,
                                           const float* __restrict__ b1,
                                           const float* __restrict__ g1,
                                           const float* __restrict__ bn1) {
    __shared__ int   s_dst[MAXEPN];
    __shared__ float s_ev[MAXEPN * 4];
    __shared__ __align__(16) float s_agg[1024];
    __shared__ float s_out[512];
    __shared__ float s_x[256];
    __shared__ float s_sA[4];
    __shared__ float s_rs[4];
    __shared__ float s_red[33];
    __shared__ int   s_m;

    int b = blockIdx.x & 1, slot = blockIdx.x >> 1, nslots = gridDim.x >> 1;
    int t = threadIdx.x, lane = t & 31, w = t >> 5;
    int nnr = min(g_nn[b], MAXNODES);
    int cnt = min(g_c1[b], MAXE1);

    for (int ln = slot; ln < nnr; ln += nslots) {
        if (t == 0) s_m = 0;
        __syncthreads();

        // collect this node's edges
        for (int i = t; i < cnt; i += 1024)
            if (g_e1src[b * MAXE1 + i] == ln) {
                int p = atomicAdd(&s_m, 1);
                if (p < MAXEPN) s_dst[p] = g_e1dst[b * MAXE1 + i];
            }
        int node = g_nodes[b * MAXNODES + ln];
        if (t < 256) s_x[t] = embed[(size_t)node * 256 + t];
        __syncthreads();
        int m = min(s_m, MAXEPN);

        // sA1[h] = emb[node].u1[h] + c1s[h]  (warp per head)
        if (w < 4) {
            float a = 0.f;
#pragma unroll
            for (int q = 0; q < 8; q++) a += s_x[lane + 32 * q] * g_u1[w * 256 + lane + 32 * q];
            a = warp_sum(a);
            if (lane == 0) s_sA[w] = a + g_c1s[w];
        }
        __syncthreads();

        // pass 1: warp per edge -> attention weights (ILP'd butterflies)
        for (int e = w; e < m; e += 32) {
            const float* er = embed + (size_t)s_dst[e] * 256;
            float emb[8];
#pragma unroll
            for (int q = 0; q < 8; q++) emb[q] = er[lane + 32 * q];
            float a4[4];
#pragma unroll
            for (int h = 0; h < 4; h++) {
                float a = 0.f;
#pragma unroll
                for (int q = 0; q < 8; q++) a += emb[q] * g_v1[h * 256 + lane + 32 * q];
                a4[h] = a;
            }
#pragma unroll
            for (int o = 16; o > 0; o >>= 1) {
#pragma unroll
                for (int h = 0; h < 4; h++) a4[h] += __shfl_xor_sync(0xffffffffu, a4[h], o);
            }
            float sel = (lane == 0) ? a4[0] : (lane == 1) ? a4[1] : (lane == 2) ? a4[2] : a4[3];
            if (lane < 4) s_ev[e * 4 + lane] = lrelu_scale_exp(s_sA[lane] + sel + g_d1s[lane]);
        }
        __syncthreads();

        // pass 2: threads 0-255 feature-parallel aggregation; warps 28-31 rowsums
        if (t < 256) {
            float a0 = 0.f, a1v = 0.f, a2v = 0.f, a3v = 0.f;
#pragma unroll 8
            for (int e = 0; e < m; e++) {
                float x = embed[(size_t)s_dst[e] * 256 + t];
                a0  += s_ev[e * 4 + 0] * x;
                a1v += s_ev[e * 4 + 1] * x;
                a2v += s_ev[e * 4 + 2] * x;
                a3v += s_ev[e * 4 + 3] * x;
            }
            s_agg[0 * 256 + t] = a0;
            s_agg[1 * 256 + t] = a1v;
            s_agg[2 * 256 + t] = a2v;
            s_agg[3 * 256 + t] = a3v;
        } else if (w >= 28) {
            int h = w - 28;
            float r = 0.f;
            for (int e = lane; e < m; e += 32) r += s_ev[e * 4 + h];
            r = warp_sum(r);
            if (lane == 0) s_rs[h] = r;
        }
        __syncthreads();

        // projection: warp per row, 16 rows/warp, float4 coalesced
#pragma unroll
        for (int i = 0; i < 16; i++) {
            int r = w + 32 * i;
            int h = r >> 7;
            const float4* wr = (const float4*)(W1 + (size_t)r * 256);
            const float4* ag = (const float4*)(s_agg + h * 256);
            float4 w0 = wr[lane], w1 = wr[lane + 32];
            float4 a0 = ag[lane], a1 = ag[lane + 32];
            float acc = w0.x * a0.x + w0.y * a0.y + w0.z * a0.z + w0.w * a0.w
                      + w1.x * a1.x + w1.y * a1.y + w1.z * a1.z + w1.w * a1.w;
            acc = warp_sum(acc);
            if (lane == 0) {
                float rs = s_rs[h];
                float rsp = (rs == 0.f) ? 1.f : rs;
                s_out[r] = (acc + rs * b1[r]) / rsp;
            }
        }
        __syncthreads();

        // layernorm(512, ddof=1, eps on std) + elu
        float val = (t < 512) ? s_out[t] : 0.f;
        float tot = block_sum(val, s_red);
        float mn = tot * (1.f / 512.f);
        float dv = (t < 512) ? (val - mn) : 0.f;
        float sq = block_sum(dv * dv, s_red);
        float stdv = sqrtf(sq * (1.f / 511.f));
        if (t < 512) {
            float y = g1[t] * dv / (stdv + LN_EPS) + bn1[t];
            g_hcat[((size_t)b * MAXNODES + ln) * 512 + t] = (y > 0.f) ? y : expm1f(y);
        }
        __syncthreads();
    }
}

// ===== K_E1: layer-2 attention + aggregation only (grid=NB) ==================
__global__ void __launch_bounds__(1024) kE1() {
    __shared__ int   s_ln[CH2];
    __shared__ float s_ev[CH2 * 4];
    __shared__ float s_x[512];
    __shared__ float s_sA[4];
    __shared__ float s_rs[4];

    int b = blockIdx.x;
    int t = threadIdx.x, lane = t & 31, w = t >> 5;
    int cnt = min(g_c2[b], MAXL2);
    int ln0 = g_map[b * NN + (NN - 1)] - 1;
    if (ln0 < 0) ln0 = 0;

    if (t < 512) s_x[t] = g_hcat[((size_t)b * MAXNODES + ln0) * 512 + t];
    if (t < 4) s_rs[t] = 0.f;
    __syncthreads();

    if (w < 4) {
        float a = 0.f;
#pragma unroll
        for (int q = 0; q < 16; q++) a += s_x[lane + 32 * q] * g_u2[w * 512 + lane + 32 * q];
        a = warp_sum(a);
        if (lane == 0) s_sA[w] = a + g_c2s[w];
    }
    __syncthreads();

    float c0 = 0.f, c1v = 0.f, c2v = 0.f, c3v = 0.f;
    for (int base = 0; base < cnt; base += CH2) {
        int mc = min(cnt - base, CH2);
        for (int e = t; e < mc; e += 1024)
            s_ln[e] = g_map[b * NN + g_l2dst[b * MAXL2 + base + e]] - 1;
        __syncthreads();

        for (int e = w; e < mc; e += 32) {
            const float* hr = g_hcat + ((size_t)b * MAXNODES + s_ln[e]) * 512;
            float hv[16];
#pragma unroll
            for (int q = 0; q < 16; q++) hv[q] = hr[lane + 32 * q];
            float a4[4];
#pragma unroll
            for (int h = 0; h < 4; h++) {
                float a = 0.f;
#pragma unroll
                for (int q = 0; q < 16; q++) a += hv[q] * g_v2[h * 512 + lane + 32 * q];
                a4[h] = a;
            }
#pragma unroll
            for (int o = 16; o > 0; o >>= 1) {
#pragma unroll
                for (int h = 0; h < 4; h++) a4[h] += __shfl_xor_sync(0xffffffffu, a4[h], o);
            }
            float sel = (lane == 0) ? a4[0] : (lane == 1) ? a4[1] : (lane == 2) ? a4[2] : a4[3];
            if (lane < 4) s_ev[e * 4 + lane] = lrelu_scale_exp(s_sA[lane] + sel + g_d2s[lane]);
        }
        __syncthreads();

        if (t < 512) {
#pragma unroll 8
            for (int e = 0; e < mc; e++) {
                float x = g_hcat[((size_t)b * MAXNODES + s_ln[e]) * 512 + t];
                c0  += s_ev[e * 4 + 0] * x;
                c1v += s_ev[e * 4 + 1] * x;
                c2v += s_ev[e * 4 + 2] * x;
                c3v += s_ev[e * 4 + 3] * x;
            }
        } else if (w >= 28) {
            int h = w - 28;
            float r = 0.f;
            for (int e = lane; e < mc; e += 32) r += s_ev[e * 4 + h];
            r = warp_sum(r);
            if (lane == 0) s_rs[h] += r;
        }
        __syncthreads();
    }
    if (t < 512) {
        g_agg2[b * 2048 + 0 * 512 + t] = c0;
        g_agg2[b * 2048 + 1 * 512 + t] = c1v;
        g_agg2[b * 2048 + 2 * 512 + t] = c2v;
        g_agg2[b * 2048 + 3 * 512 + t] = c3v;
    }
    if (t < 4) g_rs2[b * 4 + t] = s_rs[t];
}

// ===== K_E2: distributed W2 projection + last-done LN/head/cleanup ===========
__global__ void __launch_bounds__(1024) kE2(const float* __restrict__ W2,
                                            const float* __restrict__ b2,
                                            const float* __restrict__ g2,
                                            const float* __restrict__ bn2,
                                            const float* __restrict__ Vw,
                                            const float* __restrict__ Vb,
                                            float* __restrict__ out) {
    __shared__ float s_red[33];
    __shared__ int s_last;

    int b = blockIdx.x & 1;
    int chunk = blockIdx.x >> 1;             // 16 chunks of 32 rows
    int t = threadIdx.x, lane = t & 31, w = t >> 5;

    // warp-per-row projection: 32 warps -> 32 rows per block
    {
        int r = chunk * 32 + w;
        int h = r >> 7;
        const float4* wr = (const float4*)(W2 + (size_t)r * 512);
        const float4* ag = (const float4*)(g_agg2 + b * 2048 + h * 512);
        float a = 0.f;
#pragma unroll
        for (int q = 0; q < 4; q++) {
            float4 wv = wr[lane + 32 * q];
            float4 av = ag[lane + 32 * q];
            a += wv.x * av.x + wv.y * av.y + wv.z * av.z + wv.w * av.w;
        }
        a = warp_sum(a);
        if (lane == 0) {
            float rs = g_rs2[b * 4 + h];
            float rsp = (rs == 0.f) ? 1.f : rs;
            g_p[b * 512 + r] = (a + rs * b2[r]) / rsp;
        }
    }

    // last block per batch finishes: mean heads, LN(128), relu, head, cleanup
    __threadfence();
    if (t == 0) s_last = (atomicAdd(&g_done2[b], 1) == 15);
    __syncthreads();
    if (!s_last) return;
    __threadfence();

    float v = 0.f;
    if (t < 128) {
        const float* p = g_p + b * 512;
        v = 0.25f * (p[t] + p[128 + t] + p[256 + t] + p[384 + t]);
    }
    float tot = block_sum((t < 128) ? v : 0.f, s_red);
    float mn = tot * (1.f / 128.f);
    float dv = (t < 128) ? (v - mn) : 0.f;
    float sq = block_sum(dv * dv, s_red);
    float stdv = sqrtf(sq * (1.f / 127.f));
    float r0 = 0.f, r1 = 0.f;
    if (t < 128) {
        float y = g2[t] * dv / (stdv + LN_EPS) + bn2[t];
        float rr = (y > 0.f) ? y : 0.f;
        r0 = rr * Vw[t];
        r1 = rr * Vw[128 + t];
    }
    float o0 = block_sum(r0, s_red);
    float o1 = block_sum(r1, s_red);
    if (t == 0) {
        out[b * 2 + 0] = o0 + Vb[0];
        out[b * 2 + 1] = o1 + Vb[1];
    }

    // self-cleaning for next replay
    __syncthreads();
    int nnr = min(g_nn[b], MAXNODES);
    for (int i = t; i < nnr; i += 1024) g_map[b * NN + g_nodes[b * MAXNODES + i]] = 0;
    if (t == 0) {
        g_nn[b] = 0; g_c1[b] = 0; g_c2[b] = 0; g_done2[b] = 0;
        if (b == 0) g_done = 0;
    }
}

// ---------------- launch ----------------
extern "C" void kernel_launch(void* const* d_in, const int* in_sizes, int n_in,
                              void* d_out, int out_size) {
    const int* edge_in = (const int*)d_in[0];
    const int* edge_out = (const int*)d_in[1];
    const float* embed = (const float*)d_in[2];
    const float* W1 = (const float*)d_in[3];
    const float* b1 = (const float*)d_in[4];
    const float* a1 = (const float*)d_in[5];
    const float* g1 = (const float*)d_in[6];
    const float* bn1 = (const float*)d_in[7];
    const float* W2 = (const float*)d_in[8];
    const float* b2 = (const float*)d_in[9];
    const float* a2 = (const float*)d_in[10];
    const float* g2 = (const float*)d_in[11];
    const float* bn2 = (const float*)d_in[12];
    const float* Vw = (const float*)d_in[13];
    const float* Vb = (const float*)d_in[14];
    float* out = (float*)d_out;

    kA<<<512, 256>>>(edge_out, W1, b1, a1, W2, b2, a2);
    kC<<<512, 256>>>(edge_in);
    kD<<<64, 1024>>>(embed, W1, b1, g1, bn1);
    kE1<<<NB, 1024>>>();
    kE2<<<32, 1024>>>(W2, b2, g2, bn2, Vw, Vb, out);
}